// round 3
// baseline (speedup 1.0000x reference)
#include <cuda_runtime.h>
#include <cstddef>

#define H       128
#define NPL     100000
#define NTR     200000
#define NAR     50000
#define NT      350000
#define OFF_TR  100000
#define OFF_AR  300000
#define EPT     500000
#define ETA     200000
#define LBL     100000
#define GRID    152

// ---------------- scratch ----------------
__device__ float g_x  [(size_t)NT * H];
__device__ float g_y  [(size_t)NT * H];
__device__ float g_agg[(size_t)NT * H];
__device__ float g_inv[NT];
__device__ int   g_deg[NT];

// ---------------- helpers ----------------
__device__ __forceinline__ void fma2(unsigned long long& d,
                                     unsigned long long a, unsigned long long b) {
    asm("fma.rn.f32x2 %0, %1, %2, %0;" : "+l"(d) : "l"(a), "l"(b));
}

union U64F2 { unsigned long long u; float2 f; };

__device__ __forceinline__ void red4(float* p, float4 v) {
    asm volatile("red.global.add.v4.f32 [%0], {%1,%2,%3,%4};"
                 :: "l"(p), "f"(v.x), "f"(v.y), "f"(v.z), "f"(v.w) : "memory");
}

// ---------------- embedding gather (pl / ar) ----------------
__global__ void k_embed(const int* __restrict__ ids, const float* __restrict__ table,
                        const float* __restrict__ trow, float* __restrict__ out, int n)
{
    int t = blockIdx.x * blockDim.x + threadIdx.x;
    if (t >= n * 32) return;
    int i = t >> 5, c = t & 31;
    float4 v  = ((const float4*)(table + (size_t)ids[i] * H))[c];
    float4 tv = ((const float4*)trow)[c];
    v.x += tv.x; v.y += tv.y; v.z += tv.z; v.w += tv.w;
    ((float4*)(out + (size_t)i * H))[c] = v;
}

// ---------------- degree count ----------------
__global__ void k_deg(const int* __restrict__ sp, const int* __restrict__ dp,
                      const int* __restrict__ st, const int* __restrict__ dt)
{
    int e = blockIdx.x * blockDim.x + threadIdx.x;
    if (e < EPT) {
        int s = sp[e], d = dp[e] + OFF_TR;
        atomicAdd(&g_deg[d], 1);
        atomicAdd(&g_deg[s], 1);
    } else if (e < EPT + ETA) {
        int i = e - EPT;
        int s = st[i] + OFF_TR, d = dt[i] + OFF_AR;
        atomicAdd(&g_deg[d], 1);
        atomicAdd(&g_deg[s], 1);
    }
}

__global__ void k_inv()
{
    int i = blockIdx.x * blockDim.x + threadIdx.x;
    if (i < NT) g_inv[i] = 1.0f / fmaxf((float)g_deg[i], 1.0f);
}

// ---------------- edge scatter ----------------
__global__ void k_scatter(const float* __restrict__ x,
                          const int* __restrict__ sp, const int* __restrict__ dp,
                          const int* __restrict__ st, const int* __restrict__ dt)
{
    long long t = (long long)blockIdx.x * blockDim.x + threadIdx.x;
    if (t >= (long long)(EPT + ETA) * 32) return;
    int e = (int)(t >> 5), c = (int)(t & 31);
    int a, b;
    if (e < EPT) { a = sp[e];          b = dp[e] + OFF_TR; }
    else { int i = e - EPT; a = st[i] + OFF_TR; b = dt[i] + OFF_AR; }
    float4 va = ((const float4*)(x + (size_t)a * H))[c];
    float4 vb = ((const float4*)(x + (size_t)b * H))[c];
    red4(g_agg + (size_t)b * H + 4 * c, va);
    red4(g_agg + (size_t)a * H + 4 * c, vb);
}

// ---------------- f32x2 fused linear ----------------
// 256 threads, 8 warps; warp w owns nodes w*8..w*8+7 of a 64-node tile;
// lane jt owns output cols {2jt,2jt+1,64+2jt,65+2jt}.
// A-fragment LDS are warp-broadcast (crossbar-free); W-fragment traffic is
// 0.5 B/MAC -> FMA2-bound at 256 MAC/cyc/SM.
// GATHER: stage A rows from x via lrow/lcol (predictor concat).
// DOT: epilogue computes logits = wp2 . relu(h) reduced across the warp.
template<int KK, bool DUAL, bool RELU, bool SCALE, bool GATHER, bool DOT>
__global__ void __launch_bounds__(256, 1) k_linear(
    const float* __restrict__ A, const float* __restrict__ B,
    const float* __restrict__ scale,
    const float* __restrict__ W1, const float* __restrict__ W2,
    const float* __restrict__ b1, const float* __restrict__ b2,
    const int* __restrict__ lrow, const int* __restrict__ lcol,
    const float* __restrict__ wp2, const float* __restrict__ bp2,
    float* __restrict__ out, int n)
{
    extern __shared__ float sm[];
    float2* Wp  = (float2*)sm;                // (KK/2) x 128
    float*  Ash = sm + KK * 128;              // 64 x KK
    float*  bs  = Ash + 64 * KK;              // 128
    float*  w2s = bs + 128;                   // 128 (DOT)

    const int tid = threadIdx.x;

    for (int idx = tid; idx < (KK / 2) * 128; idx += 256) {
        int k2 = idx >> 7, c = idx & 127;
        const float* src;
        if (DUAL) src = (k2 < 64) ? (W1 + c * 128 + 2 * k2)
                                  : (W2 + c * 128 + 2 * (k2 - 64));
        else      src = W1 + c * KK + 2 * k2;
        Wp[idx] = *(const float2*)src;
    }
    for (int j = tid; j < 128; j += 256) {
        bs[j] = b1[j] + (b2 ? b2[j] : 0.0f);
        if (DOT) w2s[j] = wp2[j];
    }
    __syncthreads();

    const int jt = tid & 31;
    const int w  = tid >> 5;            // 0..7
    const int ntiles = (n + 63) >> 6;

    for (int tile = blockIdx.x; tile < ntiles; tile += gridDim.x) {
        const int n0 = tile << 6;
        for (int idx = tid; idx < 64 * (KK / 4); idx += 256) {
            int node = idx / (KK / 4), kc = idx % (KK / 4);
            int gn = n0 + node;
            float4 v = make_float4(0.f, 0.f, 0.f, 0.f);
            if (gn < n) {
                if (GATHER) {
                    int row = (kc < 32) ? lrow[gn] : (OFF_TR + lcol[gn]);
                    v = ((const float4*)(B + (size_t)row * 128))[kc & 31];
                } else if (DUAL) {
                    if (kc < 32) {
                        v = ((const float4*)(A + (size_t)gn * 128))[kc];
                        float s = scale[gn];
                        v.x *= s; v.y *= s; v.z *= s; v.w *= s;
                    } else {
                        v = ((const float4*)(B + (size_t)gn * 128))[kc - 32];
                    }
                } else {
                    v = ((const float4*)(A + (size_t)gn * KK))[kc];
                    if (SCALE) {
                        float s = scale[gn];
                        v.x *= s; v.y *= s; v.z *= s; v.w *= s;
                    }
                }
            }
            *(float4*)(Ash + node * KK + kc * 4) = v;
        }
        __syncthreads();

        unsigned long long acc[8][4];
        #pragma unroll
        for (int i = 0; i < 8; i++)
            #pragma unroll
            for (int c = 0; c < 4; c++) acc[i][c] = 0ull;

        const float* AshW = Ash + (w * 8) * KK;

        #pragma unroll 2
        for (int k4 = 0; k4 < KK / 4; k4++) {
            const float2* wr = Wp + (size_t)(2 * k4) * 128;
            ulonglong2 wA0 = *(const ulonglong2*)(wr + 2 * jt);
            ulonglong2 wA1 = *(const ulonglong2*)(wr + 64 + 2 * jt);
            ulonglong2 wB0 = *(const ulonglong2*)(wr + 128 + 2 * jt);
            ulonglong2 wB1 = *(const ulonglong2*)(wr + 192 + 2 * jt);
            #pragma unroll
            for (int i = 0; i < 8; i++) {
                ulonglong2 ai = *(const ulonglong2*)(AshW + i * KK + k4 * 4);
                fma2(acc[i][0], ai.x, wA0.x); fma2(acc[i][1], ai.x, wA0.y);
                fma2(acc[i][2], ai.x, wA1.x); fma2(acc[i][3], ai.x, wA1.y);
                fma2(acc[i][0], ai.y, wB0.x); fma2(acc[i][1], ai.y, wB0.y);
                fma2(acc[i][2], ai.y, wB1.x); fma2(acc[i][3], ai.y, wB1.y);
            }
        }

        #pragma unroll
        for (int i = 0; i < 8; i++) {
            int gn = n0 + w * 8 + i;
            if (gn < n) {
                float v[4];
                #pragma unroll
                for (int c = 0; c < 4; c++) {
                    U64F2 t; t.u = acc[i][c];
                    v[c] = t.f.x + t.f.y;
                }
                v[0] += bs[2 * jt];      v[1] += bs[2 * jt + 1];
                v[2] += bs[64 + 2 * jt]; v[3] += bs[65 + 2 * jt];
                if (RELU) {
                    v[0] = fmaxf(v[0], 0.f); v[1] = fmaxf(v[1], 0.f);
                    v[2] = fmaxf(v[2], 0.f); v[3] = fmaxf(v[3], 0.f);
                }
                if (DOT) {
                    float p = v[0] * w2s[2 * jt]      + v[1] * w2s[2 * jt + 1]
                            + v[2] * w2s[64 + 2 * jt] + v[3] * w2s[65 + 2 * jt];
                    #pragma unroll
                    for (int off = 16; off > 0; off >>= 1)
                        p += __shfl_xor_sync(0xffffffffu, p, off);
                    if (jt == 0) out[gn] = p + bp2[0];
                } else {
                    *(float2*)(out + (size_t)gn * 128 + 2 * jt)      = make_float2(v[0], v[1]);
                    *(float2*)(out + (size_t)gn * 128 + 64 + 2 * jt) = make_float2(v[2], v[3]);
                }
            }
        }
        __syncthreads();
    }
}

// ---------------- launch ----------------
extern "C" void kernel_launch(void* const* d_in, const int* in_sizes, int n_in,
                              void* d_out, int out_size)
{
    const int*   pl_ids   = (const int*)  d_in[0];
    const int*   ar_ids   = (const int*)  d_in[1];
    const float* track_x  = (const float*)d_in[2];
    const int*   src_pt   = (const int*)  d_in[3];
    const int*   dst_pt   = (const int*)  d_in[4];
    const int*   src_ta   = (const int*)  d_in[5];
    const int*   dst_ta   = (const int*)  d_in[6];
    const int*   lab_row  = (const int*)  d_in[7];
    const int*   lab_col  = (const int*)  d_in[8];
    const float* pl_table = (const float*)d_in[9];
    const float* ar_table = (const float*)d_in[10];
    const float* Wtr      = (const float*)d_in[11];
    const float* btr      = (const float*)d_in[12];
    const float* type_tab = (const float*)d_in[13];
    const float* Wl0      = (const float*)d_in[14];
    const float* bl0      = (const float*)d_in[15];
    const float* Wr0      = (const float*)d_in[16];
    const float* Wl1      = (const float*)d_in[17];
    const float* bl1      = (const float*)d_in[18];
    const float* Wr1      = (const float*)d_in[19];
    const float* Wp1      = (const float*)d_in[20];
    const float* bp1      = (const float*)d_in[21];
    const float* Wp2      = (const float*)d_in[22];
    const float* bp2      = (const float*)d_in[23];
    float* out = (float*)d_out;

    float *x, *y, *agg, *inv; int* deg;
    cudaGetSymbolAddress((void**)&x,   g_x);
    cudaGetSymbolAddress((void**)&y,   g_y);
    cudaGetSymbolAddress((void**)&agg, g_agg);
    cudaGetSymbolAddress((void**)&inv, g_inv);
    cudaGetSymbolAddress((void**)&deg, g_deg);

    const int SMEM_256 = (256 * 128 + 64 * 256 + 256) * 4;   // 197632
    const int SMEM_128 = (128 * 128 + 64 * 128 + 256) * 4;   // 99328

    cudaFuncSetAttribute(k_linear<256, true,  true,  true,  false, false>, cudaFuncAttributeMaxDynamicSharedMemorySize, SMEM_256);
    cudaFuncSetAttribute(k_linear<256, false, true,  false, true,  true >, cudaFuncAttributeMaxDynamicSharedMemorySize, SMEM_256);
    cudaFuncSetAttribute(k_linear<128, false, false, false, false, false>, cudaFuncAttributeMaxDynamicSharedMemorySize, SMEM_128);

    // ---- degrees first (also puts interesting kernels at ncu's -s 5) ----
    cudaMemsetAsync(deg, 0, (size_t)NT * sizeof(int));
    k_deg<<<(EPT + ETA + 255) / 256, 256>>>(src_pt, dst_pt, src_ta, dst_ta);
    k_inv<<<(NT + 255) / 256, 256>>>();

    // ---- encode ----
    k_embed<<<(NPL * 32 + 255) / 256, 256>>>(pl_ids, pl_table, type_tab, x, NPL);
    k_embed<<<(NAR * 32 + 255) / 256, 256>>>(ar_ids, ar_table, type_tab + 2 * H,
                                             x + (size_t)OFF_AR * H, NAR);
    k_linear<128, false, false, false, false, false><<<GRID, 256, SMEM_128>>>(
        track_x, nullptr, nullptr, Wtr, nullptr, btr, type_tab + H,
        nullptr, nullptr, nullptr, nullptr, x + (size_t)OFF_TR * H, NTR);

    const long long sc_threads = (long long)(EPT + ETA) * 32;
    const int sc_blocks = (int)((sc_threads + 255) / 256);

    // ---- layer 0 ----
    cudaMemsetAsync(agg, 0, (size_t)NT * H * sizeof(float));
    k_scatter<<<sc_blocks, 256>>>(x, src_pt, dst_pt, src_ta, dst_ta);
    k_linear<256, true, true, true, false, false><<<GRID, 256, SMEM_256>>>(
        agg, x, inv, Wl0, Wr0, bl0, nullptr,
        nullptr, nullptr, nullptr, nullptr, y, NT);

    // ---- layer 1 ----
    cudaMemsetAsync(agg, 0, (size_t)NT * H * sizeof(float));
    k_scatter<<<sc_blocks, 256>>>(y, src_pt, dst_pt, src_ta, dst_ta);
    k_linear<256, true, true, true, false, false><<<GRID, 256, SMEM_256>>>(
        agg, y, inv, Wl1, Wr1, bl1, nullptr,
        nullptr, nullptr, nullptr, nullptr, x, NT);

    // ---- predictor (gather + GEMM + dot fused) ----
    k_linear<256, false, true, false, true, true><<<GRID, 256, SMEM_256>>>(
        nullptr, x, nullptr, Wp1, nullptr, bp1, nullptr,
        lab_row, lab_col, Wp2, bp2, out, LBL);
}